// round 1
// baseline (speedup 1.0000x reference)
#include <cuda_runtime.h>
#include <cstdint>

#define NB 8
#define NC 64
#define NPTS 16384
#define MODES 32
#define NJ 128                 // 2 branches * 2 comps(cos,sin) * 32 modes
#define NCH 32                 // forward n-chunks
#define FWD_CHUNK (NPTS / NCH) // 512
#define FWD_TS 32
#define NCHI 16                // inverse n-chunks
#define INV_CHUNK (NPTS / NCHI) // 1024
#define INV_TS 64
#define INV_BAS_STRIDE (INV_TS + 4) // 68, multiple of 4 for float4
#define TWO_PI_F 6.28318530717958647692f

// scratch (no allocations allowed): fwd partials + mixed modes
__device__ float g_FTp[(size_t)NB * NCH * NJ * NC]; // 8*32*128*64 = 2,097,152 floats (8 MB)
__device__ float g_MY[(size_t)NB * NJ * NC];        // 8*128*64    = 65,536 floats

// ---------------------------------------------------------------------------
// Forward: FTp[b][ch][j][c] = sum over chunk n of x[b,c,n] * Bas_in[j,n]
//   j = br*64 + cs*32 + k ;  cs=0 -> cos(2*pi*k*p), cs=1 -> sin(2*pi*k*p)
//   p = x_in[b][n][br]
// ---------------------------------------------------------------------------
__global__ __launch_bounds__(256) void fwd_kernel(const float* __restrict__ x,
                                                  const float* __restrict__ x_in) {
    __shared__ float xs[NC][FWD_TS + 4];   // stride 36: float4-aligned rows, conflict-free reads
    __shared__ float bas[NJ][FWD_TS + 1];  // stride 33

    const int b  = blockIdx.y;
    const int ch = blockIdx.x;
    const int tid = threadIdx.x;
    const int nbase = ch * FWD_CHUNK;

    const int ct = tid & 7;        // thread's c set: {ct, ct+8, ..., ct+56}
    const int j0 = (tid >> 3) * 4; // 4 consecutive j

    float acc[8][4];
#pragma unroll
    for (int i = 0; i < 8; ++i)
#pragma unroll
        for (int jj = 0; jj < 4; ++jj) acc[i][jj] = 0.f;

    const int stage_c  = tid >> 2;
    const int stage_nq = (tid & 3) * 8;
    const float* xrow = x + ((size_t)(b * NC + stage_c)) * NPTS;

    for (int sub = 0; sub < FWD_CHUNK / FWD_TS; ++sub) {
        const int n0 = nbase + sub * FWD_TS;
        __syncthreads();
        // stage x tile [64 c][32 n]
        {
            const float4* gx = reinterpret_cast<const float4*>(xrow + n0 + stage_nq);
            float4 v0 = gx[0];
            float4 v1 = gx[1];
            *reinterpret_cast<float4*>(&xs[stage_c][stage_nq])     = v0;
            *reinterpret_cast<float4*>(&xs[stage_c][stage_nq + 4]) = v1;
        }
        // stage basis [128 j][32 n] : 2048 sincos values, 8 per thread
        {
#pragma unroll
            for (int rep = 0; rep < 8; ++rep) {
                int v  = tid + rep * 256;       // 0..2047
                int n  = v & (FWD_TS - 1);
                int k  = (v >> 5) & (MODES - 1);
                int br = v >> 10;
                float p = x_in[((size_t)(b * NPTS + n0 + n)) * 2 + br];
                float f = (float)k * p;
                f -= rintf(f);                  // range-reduce to [-0.5, 0.5]
                float s, c;
                __sincosf(TWO_PI_F * f, &s, &c);
                bas[br * 64 + k][n]      = c;
                bas[br * 64 + 32 + k][n] = s;
            }
        }
        __syncthreads();
#pragma unroll 4
        for (int n = 0; n < FWD_TS; ++n) {
            float bx[8], bb[4];
#pragma unroll
            for (int i = 0; i < 8; ++i) bx[i] = xs[ct + 8 * i][n];
#pragma unroll
            for (int jj = 0; jj < 4; ++jj) bb[jj] = bas[j0 + jj][n];
#pragma unroll
            for (int i = 0; i < 8; ++i)
#pragma unroll
                for (int jj = 0; jj < 4; ++jj)
                    acc[i][jj] = fmaf(bx[i], bb[jj], acc[i][jj]);
        }
    }

    float* outp = g_FTp + ((size_t)(b * NCH + ch)) * NJ * NC;
#pragma unroll
    for (int jj = 0; jj < 4; ++jj)
#pragma unroll
        for (int i = 0; i < 8; ++i)
            outp[(j0 + jj) * NC + ct + 8 * i] = acc[i][jj];
}

// ---------------------------------------------------------------------------
// Mix: reduce chunk partials, apply complex weights, fold signs and scale 64.
//  forward uses e^{-i th}: fty = (Ac, -As)
//  my_r = sum_i Ac*Wr + As*Wi ;  my_i = sum_i Ac*Wi - As*Wr
//  inverse uses e^{+i th'}: contribution = 64*(my_r*cos - my_i*sin)
//  store MY[j= br*64+0*32+k][o] = 64*my_r ; MY[br*64+32+k][o] = -64*my_i
// ---------------------------------------------------------------------------
__global__ __launch_bounds__(64) void mix_kernel(const float* __restrict__ w1,
                                                 const float* __restrict__ w2) {
    const int k  = blockIdx.x;
    const int br = blockIdx.y;
    const int b  = blockIdx.z;
    const int o  = threadIdx.x;

    __shared__ float Ac[NC], As[NC];

    for (int v = threadIdx.x; v < 2 * NC; v += 64) {
        int cs = v >> 6;
        int i  = v & 63;
        int j  = br * 64 + cs * 32 + k;
        float s = 0.f;
        const float* base = g_FTp + (size_t)b * NCH * NJ * NC + (size_t)j * NC + i;
        for (int c2 = 0; c2 < NCH; ++c2) s += base[(size_t)c2 * NJ * NC];
        if (cs == 0) Ac[i] = s; else As[i] = s;
    }
    __syncthreads();

    const float* W = (br == 0) ? w1 : w2;
    float mr = 0.f, mi = 0.f;
    for (int i = 0; i < NC; ++i) {
        float2 w = *reinterpret_cast<const float2*>(W + (((size_t)i * 64 + o) * 32 + k) * 2);
        float ac = Ac[i], as = As[i];
        mr = fmaf(ac, w.x, mr);
        mr = fmaf(as, w.y, mr);
        mi = fmaf(ac, w.y, mi);
        mi = fmaf(-as, w.x, mi);
    }
    g_MY[((size_t)b * NJ + br * 64 + k) * NC + o]      = 64.f * mr;
    g_MY[((size_t)b * NJ + br * 64 + 32 + k) * NC + o] = -64.f * mi;
}

// ---------------------------------------------------------------------------
// Inverse: out[b][o][n] = sum_j MY[b][j][o] * Bas_out[j][n]
// register-blocked 4o x 4n GEMM; MY + basis tile in dynamic smem.
// ---------------------------------------------------------------------------
__device__ __forceinline__ float4 fma4(float s, float4 v, float4 a) {
    a.x = fmaf(s, v.x, a.x);
    a.y = fmaf(s, v.y, a.y);
    a.z = fmaf(s, v.z, a.z);
    a.w = fmaf(s, v.w, a.w);
    return a;
}

__global__ __launch_bounds__(256) void inv_kernel(const float* __restrict__ x_out,
                                                  float* __restrict__ out) {
    extern __shared__ float sm[];
    float* Bas = sm;                       // [NJ][INV_BAS_STRIDE]
    float* MYs = sm + NJ * INV_BAS_STRIDE; // [NJ][64] (16B-aligned offset)
    __shared__ float ps[2][INV_TS];

    const int b  = blockIdx.y;
    const int ch = blockIdx.x;
    const int tid = threadIdx.x;
    const int nbase = ch * INV_CHUNK;

    // load MY matrix for this batch (once)
    {
        const float* src = g_MY + (size_t)b * NJ * NC;
        for (int v = tid; v < NJ * NC; v += 256) MYs[v] = src[v];
    }

    const int nq = (tid & 15) * 4;   // 4 consecutive n
    const int o0 = (tid >> 4) * 4;   // 4 consecutive o

    for (int sub = 0; sub < INV_CHUNK / INV_TS; ++sub) {
        const int n0 = nbase + sub * INV_TS;
        __syncthreads();
        if (tid < 128) {
            int br = tid >> 6;
            int n  = tid & 63;
            ps[br][n] = x_out[((size_t)(b * NPTS + n0 + n)) * 2 + br];
        }
        __syncthreads();
        // basis gen: 2*32*64 = 4096 sincos, 16 per thread
#pragma unroll
        for (int rep = 0; rep < 16; ++rep) {
            int v  = tid + rep * 256;
            int n  = v & 63;
            int k  = (v >> 6) & 31;
            int br = v >> 11;
            float p = ps[br][n];
            float f = (float)k * p;
            f -= rintf(f);
            float s, c;
            __sincosf(TWO_PI_F * f, &s, &c);
            Bas[(br * 64 + k) * INV_BAS_STRIDE + n]      = c;
            Bas[(br * 64 + 32 + k) * INV_BAS_STRIDE + n] = s;
        }
        __syncthreads();

        float4 a0 = make_float4(0.f, 0.f, 0.f, 0.f);
        float4 a1 = a0, a2 = a0, a3 = a0;
#pragma unroll 8
        for (int j = 0; j < NJ; ++j) {
            float4 bv = *reinterpret_cast<float4*>(&Bas[j * INV_BAS_STRIDE + nq]);
            float4 mv = *reinterpret_cast<float4*>(&MYs[j * 64 + o0]);
            a0 = fma4(mv.x, bv, a0);
            a1 = fma4(mv.y, bv, a1);
            a2 = fma4(mv.z, bv, a2);
            a3 = fma4(mv.w, bv, a3);
        }
        float* orow = out + ((size_t)(b * NC + o0)) * NPTS + n0 + nq;
        *reinterpret_cast<float4*>(orow)             = a0;
        *reinterpret_cast<float4*>(orow + NPTS)      = a1;
        *reinterpret_cast<float4*>(orow + 2 * NPTS)  = a2;
        *reinterpret_cast<float4*>(orow + 3 * NPTS)  = a3;
    }
}

// ---------------------------------------------------------------------------
extern "C" void kernel_launch(void* const* d_in, const int* in_sizes, int n_in,
                              void* d_out, int out_size) {
    const float* x     = (const float*)d_in[0];
    const float* x_in  = (const float*)d_in[1];
    const float* x_out = (const float*)d_in[2];
    const float* w1    = (const float*)d_in[3];
    const float* w2    = (const float*)d_in[4];
    float* out = (float*)d_out;

    const int inv_smem = (NJ * INV_BAS_STRIDE + NJ * NC) * (int)sizeof(float); // 67584 B
    cudaFuncSetAttribute(inv_kernel, cudaFuncAttributeMaxDynamicSharedMemorySize, inv_smem);

    fwd_kernel<<<dim3(NCH, NB), 256>>>(x, x_in);
    mix_kernel<<<dim3(MODES, 2, NB), 64>>>(w1, w2);
    inv_kernel<<<dim3(NCHI, NB), 256, inv_smem>>>(x_out, out);
}

// round 2
// speedup vs baseline: 1.1346x; 1.1346x over previous
#include <cuda_runtime.h>
#include <cstdint>

#define NB 8
#define NC 64
#define NPTS 16384
#define MODES 32
#define NJ 128                 // 2 branches * 2 comps(cos,sin) * 32 modes
#define NJ2 64                 // 2 branches * 32 complex modes
#define NCH 32                 // forward n-chunks
#define FWD_CHUNK (NPTS / NCH) // 512
#define FWD_TS 32
#define NCHI 32                // inverse n-chunks
#define INV_CHUNK (NPTS / NCHI) // 512
#define INV_TS 128             // n per inner subtile
#define BAS_S (2 * INV_TS + 2) // 258 floats, even (8B-aligned rows)
#define TWO_PI_F 6.28318530717958647692f

typedef unsigned long long u64;

// scratch (no allocations allowed): fwd partials + mixed modes
__device__ float g_FTp[(size_t)NB * NCH * NJ * NC]; // 8 MB
__device__ float g_MY[(size_t)NB * NJ * NC];        // 256 KB

__device__ __forceinline__ void ffma2(u64& d, u64 a, u64 b) {
    asm("fma.rn.f32x2 %0, %1, %2, %0;" : "+l"(d) : "l"(a), "l"(b));
}
__device__ __forceinline__ float hadd2(u64 a) {
    float lo, hi;
    asm("mov.b64 {%0, %1}, %2;" : "=f"(lo), "=f"(hi) : "l"(a));
    return lo + hi;
}

// ---------------------------------------------------------------------------
// Forward: FTp[b][ch][j][c] = sum over chunk n of x[b,c,n] * Bas_in[j,n]
//   j = br*64 + cs*32 + k ;  cs=0 -> cos(2 pi k p), cs=1 -> sin(2 pi k p)
//   p = x_in[b][n][br].  Packed f32x2 over n-pairs.
// ---------------------------------------------------------------------------
__global__ __launch_bounds__(256, 2) void fwd_kernel(const float* __restrict__ x,
                                                     const float* __restrict__ x_in) {
    __shared__ float xs[NC][FWD_TS + 4];   // stride 36 (even, float4-aligned)
    __shared__ float bas[NJ][FWD_TS + 2];  // stride 34 (even -> 8B-aligned pairs)

    const int b  = blockIdx.y;
    const int ch = blockIdx.x;
    const int tid = threadIdx.x;
    const int nbase = ch * FWD_CHUNK;

    const int ct = tid & 7;        // c set: {ct, ct+8, ..., ct+56}
    const int j0 = (tid >> 3) * 4; // 4 consecutive j

    u64 acc[8][4];
#pragma unroll
    for (int i = 0; i < 8; ++i)
#pragma unroll
        for (int jj = 0; jj < 4; ++jj) acc[i][jj] = 0ull;

    const int stage_c  = tid >> 2;
    const int stage_nq = (tid & 3) * 8;
    const float* xrow = x + ((size_t)(b * NC + stage_c)) * NPTS;

    for (int sub = 0; sub < FWD_CHUNK / FWD_TS; ++sub) {
        const int n0 = nbase + sub * FWD_TS;
        __syncthreads();
        // stage x tile [64 c][32 n]
        {
            const float4* gx = reinterpret_cast<const float4*>(xrow + n0 + stage_nq);
            float4 v0 = gx[0];
            float4 v1 = gx[1];
            *reinterpret_cast<float4*>(&xs[stage_c][stage_nq])     = v0;
            *reinterpret_cast<float4*>(&xs[stage_c][stage_nq + 4]) = v1;
        }
        // stage basis [128 j][32 n] : 2048 sincos values, 8 per thread
#pragma unroll
        for (int rep = 0; rep < 8; ++rep) {
            int v  = tid + rep * 256;       // 0..2047
            int n  = v & (FWD_TS - 1);
            int k  = (v >> 5) & (MODES - 1);
            int br = v >> 10;
            float p = x_in[((size_t)(b * NPTS + n0 + n)) * 2 + br];
            float f = (float)k * p;
            f -= rintf(f);                  // range-reduce to [-0.5, 0.5]
            float s, c;
            __sincosf(TWO_PI_F * f, &s, &c);
            bas[br * 64 + k][n]      = c;
            bas[br * 64 + 32 + k][n] = s;
        }
        __syncthreads();
#pragma unroll 4
        for (int np = 0; np < FWD_TS / 2; ++np) {
            const int n2 = np * 2;
            u64 bx[8], bb[4];
#pragma unroll
            for (int i = 0; i < 8; ++i)
                bx[i] = *reinterpret_cast<const u64*>(&xs[ct + 8 * i][n2]);
#pragma unroll
            for (int jj = 0; jj < 4; ++jj)
                bb[jj] = *reinterpret_cast<const u64*>(&bas[j0 + jj][n2]);
#pragma unroll
            for (int i = 0; i < 8; ++i)
#pragma unroll
                for (int jj = 0; jj < 4; ++jj)
                    ffma2(acc[i][jj], bx[i], bb[jj]);
        }
    }

    float* outp = g_FTp + ((size_t)(b * NCH + ch)) * NJ * NC;
#pragma unroll
    for (int jj = 0; jj < 4; ++jj)
#pragma unroll
        for (int i = 0; i < 8; ++i)
            outp[(j0 + jj) * NC + ct + 8 * i] = hadd2(acc[i][jj]);
}

// ---------------------------------------------------------------------------
// Mix: reduce chunk partials, apply complex weights, fold signs and scale 64.
//  store MY[br*64+k][o] = 64*my_r ; MY[br*64+32+k][o] = -64*my_i
// ---------------------------------------------------------------------------
__global__ __launch_bounds__(64) void mix_kernel(const float* __restrict__ w1,
                                                 const float* __restrict__ w2) {
    const int k  = blockIdx.x;
    const int br = blockIdx.y;
    const int b  = blockIdx.z;
    const int o  = threadIdx.x;

    __shared__ float Ac[NC], As[NC];

    for (int v = threadIdx.x; v < 2 * NC; v += 64) {
        int cs = v >> 6;
        int i  = v & 63;
        int j  = br * 64 + cs * 32 + k;
        float s = 0.f;
        const float* base = g_FTp + (size_t)b * NCH * NJ * NC + (size_t)j * NC + i;
        for (int c2 = 0; c2 < NCH; ++c2) s += base[(size_t)c2 * NJ * NC];
        if (cs == 0) Ac[i] = s; else As[i] = s;
    }
    __syncthreads();

    const float* W = (br == 0) ? w1 : w2;
    float mr = 0.f, mi = 0.f;
    for (int i = 0; i < NC; ++i) {
        float2 w = *reinterpret_cast<const float2*>(W + (((size_t)i * 64 + o) * 32 + k) * 2);
        float ac = Ac[i], as = As[i];
        mr = fmaf(ac, w.x, mr);
        mr = fmaf(as, w.y, mr);
        mi = fmaf(ac, w.y, mi);
        mi = fmaf(-as, w.x, mi);
    }
    g_MY[((size_t)b * NJ + br * 64 + k) * NC + o]      = 64.f * mr;
    g_MY[((size_t)b * NJ + br * 64 + 32 + k) * NC + o] = -64.f * mi;
}

// ---------------------------------------------------------------------------
// Inverse: out[b][o][n] = sum_{j2} ( MYr[j2][o]*cos + MYs[j2][o]*sin )
// Complex-packed f32x2: MYc[j2][o] = (64*mr, -64*mi), Basc[j2][n] = (cos, sin).
// Thread tile 4o x 8n (n strided by 16 for conflict-free LDS.64).
// ---------------------------------------------------------------------------
__global__ __launch_bounds__(256, 2) void inv_kernel(const float* __restrict__ x_out,
                                                     float* __restrict__ out) {
    extern __shared__ float sm[];
    float* Basc = sm;                  // [NJ2][BAS_S]
    float* MYc  = sm + NJ2 * BAS_S;    // [NJ2][NC*2]
    __shared__ float ps[2][INV_TS];

    const int b  = blockIdx.y;
    const int ch = blockIdx.x;
    const int tid = threadIdx.x;
    const int nbase = ch * INV_CHUNK;

    // build interleaved MY for this batch (once)
    {
        const float* src = g_MY + (size_t)b * NJ * NC;
        for (int v = tid; v < NJ2 * NC * 2; v += 256) {
            int j2   = v >> 7;          // 0..63
            int rest = v & 127;
            int o    = rest >> 1;
            int comp = rest & 1;        // 0 -> mr part, 1 -> -mi part
            int br   = j2 >> 5;
            int k    = j2 & 31;
            MYc[v] = src[(br * 64 + comp * 32 + k) * NC + o];
        }
    }

    const int nt = tid & 15;        // n = nt + 16*d
    const int o0 = (tid >> 4) * 4;  // 4 consecutive o

    for (int sub = 0; sub < INV_CHUNK / INV_TS; ++sub) {
        const int n0 = nbase + sub * INV_TS;
        __syncthreads();
        // stage mapped coords
        {
            int n  = tid >> 1;
            int br = tid & 1;
            ps[br][n] = x_out[((size_t)(b * NPTS + n0 + n)) * 2 + br];
        }
        __syncthreads();
        // basis gen: 2*32*128 = 8192 sincos, 32 per thread
#pragma unroll
        for (int rep = 0; rep < 32; ++rep) {
            int v  = tid + rep * 256;
            int n  = v & 127;
            int k  = (v >> 7) & 31;
            int br = v >> 12;
            float p = ps[br][n];
            float f = (float)k * p;
            f -= rintf(f);
            float s, c;
            __sincosf(TWO_PI_F * f, &s, &c);
            Basc[(br * 32 + k) * BAS_S + 2 * n]     = c;
            Basc[(br * 32 + k) * BAS_S + 2 * n + 1] = s;
        }
        __syncthreads();

        u64 acc[4][8];
#pragma unroll
        for (int oo = 0; oo < 4; ++oo)
#pragma unroll
            for (int d = 0; d < 8; ++d) acc[oo][d] = 0ull;

#pragma unroll 4
        for (int j2 = 0; j2 < NJ2; ++j2) {
            u64 bv[8];
#pragma unroll
            for (int d = 0; d < 8; ++d)
                bv[d] = *reinterpret_cast<const u64*>(&Basc[j2 * BAS_S + 2 * (nt + 16 * d)]);
            ulonglong2 mva = *reinterpret_cast<const ulonglong2*>(&MYc[j2 * (NC * 2) + o0 * 2]);
            ulonglong2 mvb = *reinterpret_cast<const ulonglong2*>(&MYc[j2 * (NC * 2) + o0 * 2 + 4]);
            u64 mv0 = mva.x, mv1 = mva.y, mv2 = mvb.x, mv3 = mvb.y;
#pragma unroll
            for (int d = 0; d < 8; ++d) {
                ffma2(acc[0][d], mv0, bv[d]);
                ffma2(acc[1][d], mv1, bv[d]);
                ffma2(acc[2][d], mv2, bv[d]);
                ffma2(acc[3][d], mv3, bv[d]);
            }
        }

#pragma unroll
        for (int oo = 0; oo < 4; ++oo) {
            float* orow = out + ((size_t)(b * NC + o0 + oo)) * NPTS + n0 + nt;
#pragma unroll
            for (int d = 0; d < 8; ++d)
                orow[16 * d] = hadd2(acc[oo][d]);
        }
    }
}

// ---------------------------------------------------------------------------
extern "C" void kernel_launch(void* const* d_in, const int* in_sizes, int n_in,
                              void* d_out, int out_size) {
    const float* x     = (const float*)d_in[0];
    const float* x_in  = (const float*)d_in[1];
    const float* x_out = (const float*)d_in[2];
    const float* w1    = (const float*)d_in[3];
    const float* w2    = (const float*)d_in[4];
    float* out = (float*)d_out;

    const int inv_smem = (NJ2 * BAS_S + NJ2 * NC * 2) * (int)sizeof(float); // 98816 B
    cudaFuncSetAttribute(inv_kernel, cudaFuncAttributeMaxDynamicSharedMemorySize, inv_smem);

    fwd_kernel<<<dim3(NCH, NB), 256>>>(x, x_in);
    mix_kernel<<<dim3(MODES, 2, NB), 64>>>(w1, w2);
    inv_kernel<<<dim3(NCHI, NB), 256, inv_smem>>>(x_out, out);
}

// round 4
// speedup vs baseline: 2.0940x; 1.8456x over previous
#include <cuda_runtime.h>
#include <cuda_bf16.h>
#include <cstdint>

#define NB 8
#define NC 64
#define NPTS 16384
#define NJ 128
#define NCH 32
#define FWD_CHUNK 512
#define FWD_TN 64
#define FWD_TILES 8
#define NCHI 32
#define INV_CHUNK 512
#define INV_TN 128
#define INV_TILES 4
#define TWO_PI_F 6.28318530717958647692f

#define FWD_AS 72   // row stride (elems) for fwd smem tiles (144 B)
#define INV_S 136   // row stride (elems) for inv smem tiles (272 B)

// fwd smem offsets (bytes)
#define F_AHI 0
#define F_ALO 18432
#define F_BHI 36864
#define F_BLO 46080
#define F_TOT 55296
// inv smem offsets
#define I_AHI 0          // MY hi   [64 o][136]
#define I_ALO 17408
#define I_BHI 34816      // basis hi [128 n][136]
#define I_BLO 69632
#define I_TOT 104448

__device__ float g_FTp[(size_t)NB * NCH * NJ * NC]; // 8 MB
__device__ float g_MY[(size_t)NB * NJ * NC];        // 256 KB

extern __shared__ __align__(16) char dsm[];

// ---------------------------------------------------------------------------
// helpers
// ---------------------------------------------------------------------------
__device__ __forceinline__ uint32_t smem_u32(const void* p) {
    uint32_t a;
    asm("{ .reg .u64 t; cvta.to.shared.u64 t, %1; cvt.u32.u64 %0, t; }" : "=r"(a) : "l"(p));
    return a;
}
__device__ __forceinline__ void ldsm4(uint32_t* r, uint32_t addr) {
    asm volatile("ldmatrix.sync.aligned.m8n8.x4.shared.b16 {%0,%1,%2,%3}, [%4];"
                 : "=r"(r[0]), "=r"(r[1]), "=r"(r[2]), "=r"(r[3]) : "r"(addr));
}
__device__ __forceinline__ void mma_bf16(float* d, const uint32_t* a, uint32_t b0, uint32_t b1) {
    asm volatile("mma.sync.aligned.m16n8k16.row.col.f32.bf16.bf16.f32 "
                 "{%0,%1,%2,%3}, {%4,%5,%6,%7}, {%8,%9}, {%0,%1,%2,%3};"
                 : "+f"(d[0]), "+f"(d[1]), "+f"(d[2]), "+f"(d[3])
                 : "r"(a[0]), "r"(a[1]), "r"(a[2]), "r"(a[3]), "r"(b0), "r"(b1));
}
__device__ __forceinline__ void split_bf16(float v, __nv_bfloat16& h, __nv_bfloat16& l) {
    h = __float2bfloat16_rn(v);
    l = __float2bfloat16_rn(v - __bfloat162float(h));
}
__device__ __forceinline__ uint32_t pk2(__nv_bfloat16 a, __nv_bfloat16 b) {
    return (uint32_t)__bfloat16_as_ushort(a) | ((uint32_t)__bfloat16_as_ushort(b) << 16);
}

// ---------------------------------------------------------------------------
// Forward: g_FTp[b][ch][j=128][c=64] = sum_n Bas[j][n] * x[c][n], n in 512-chunk
// A = basis [128 j][64 n] bf16 hi/lo, B = x [64 c][64 n]. 3-pass hi/lo HMMA.
// ---------------------------------------------------------------------------
__global__ __launch_bounds__(256) void fwd_kernel(const float* __restrict__ x,
                                                  const float* __restrict__ x_in) {
    const int b = blockIdx.y, ch = blockIdx.x;
    const int tid = threadIdx.x, wid = tid >> 5, lane = tid & 31;

    __nv_bfloat16* AH = (__nv_bfloat16*)(dsm + F_AHI);
    __nv_bfloat16* AL = (__nv_bfloat16*)(dsm + F_ALO);
    __nv_bfloat16* BH = (__nv_bfloat16*)(dsm + F_BHI);
    __nv_bfloat16* BL = (__nv_bfloat16*)(dsm + F_BLO);

    const int j0 = (wid >> 2) * 64;
    const int c0 = (wid & 3) * 16;

    // ldmatrix lane addresses (bytes into smem)
    const uint32_t a_row = (uint32_t)(j0 + (lane & 7) + ((lane >> 3) & 1) * 8);
    const uint32_t a_col = (uint32_t)((lane >> 4) * 8);
    const uint32_t b_row = (uint32_t)(c0 + (lane & 7) + ((lane >> 3) & 1) * 8);
    const uint32_t base = smem_u32(dsm);
    const uint32_t AHIa = base + F_AHI + (a_row * FWD_AS + a_col) * 2;
    const uint32_t ALOa = base + F_ALO + (a_row * FWD_AS + a_col) * 2;
    const uint32_t BHIa = base + F_BHI + (b_row * FWD_AS + a_col) * 2;
    const uint32_t BLOa = base + F_BLO + (b_row * FWD_AS + a_col) * 2;

    // staging params
    const int cc = tid >> 2;
    const int nq = (tid & 3) * 16;
    const float* xr = x + ((size_t)b * NC + cc) * NPTS;

    // basis chain params: 1 chain per thread (n 0-63, br 0-1, khalf 0-1)
    const int cn  = tid & 63;
    const int cbr = (tid >> 6) & 1;
    const int ckh = tid >> 7;
    const int jc = cbr * 64 + ckh * 16; // cos rows
    const int js = jc + 32;             // sin rows

    float acc[4][2][4];
#pragma unroll
    for (int mi = 0; mi < 4; ++mi)
#pragma unroll
        for (int ni = 0; ni < 2; ++ni)
#pragma unroll
            for (int q = 0; q < 4; ++q) acc[mi][ni][q] = 0.f;

    for (int t = 0; t < FWD_TILES; ++t) {
        const int n0 = ch * FWD_CHUNK + t * FWD_TN;
        __syncthreads();
        // --- stage x tile ---
#pragma unroll
        for (int g = 0; g < 4; ++g) {
            float4 v = *reinterpret_cast<const float4*>(xr + n0 + nq + 4 * g);
            __nv_bfloat16 h0, l0, h1, l1, h2, l2, h3, l3;
            split_bf16(v.x, h0, l0); split_bf16(v.y, h1, l1);
            split_bf16(v.z, h2, l2); split_bf16(v.w, h3, l3);
            int col = nq + 4 * g;
            *reinterpret_cast<uint32_t*>(&BH[cc * FWD_AS + col])     = pk2(h0, h1);
            *reinterpret_cast<uint32_t*>(&BL[cc * FWD_AS + col])     = pk2(l0, l1);
            *reinterpret_cast<uint32_t*>(&BH[cc * FWD_AS + col + 2]) = pk2(h2, h3);
            *reinterpret_cast<uint32_t*>(&BL[cc * FWD_AS + col + 2]) = pk2(l2, l3);
        }
        // --- stage basis via recurrence chain ---
        {
            float p = x_in[((size_t)b * NPTS + n0 + cn) * 2 + cbr];
            float c1r, c1i;
            {
                float f = p - rintf(p);
                __sincosf(TWO_PI_F * f, &c1i, &c1r);
            }
            float cr, ci;
            if (ckh == 0) { cr = 1.f; ci = 0.f; }
            else {
                float f = 16.f * p;
                f -= rintf(f);
                __sincosf(TWO_PI_F * f, &ci, &cr);
            }
#pragma unroll
            for (int k = 0; k < 16; ++k) {
                __nv_bfloat16 hc, lc, hs, ls;
                split_bf16(cr, hc, lc);
                split_bf16(ci, hs, ls);
                AH[(jc + k) * FWD_AS + cn] = hc;
                AL[(jc + k) * FWD_AS + cn] = lc;
                AH[(js + k) * FWD_AS + cn] = hs;
                AL[(js + k) * FWD_AS + cn] = ls;
                float nr = fmaf(cr, c1r, -ci * c1i);
                float ni_ = fmaf(cr, c1i, ci * c1r);
                cr = nr; ci = ni_;
            }
        }
        __syncthreads();
        // --- MMA over 4 k-steps of 16 ---
#pragma unroll
        for (int ks = 0; ks < 4; ++ks) {
            const uint32_t co = (uint32_t)(ks * 16 * 2);
            uint32_t ah[4][4], al[4][4], bh[4], bl[4];
#pragma unroll
            for (int mi = 0; mi < 4; ++mi) {
                ldsm4(ah[mi], AHIa + mi * (16 * FWD_AS * 2) + co);
                ldsm4(al[mi], ALOa + mi * (16 * FWD_AS * 2) + co);
            }
            ldsm4(bh, BHIa + co);
            ldsm4(bl, BLOa + co);
#pragma unroll
            for (int mi = 0; mi < 4; ++mi)
#pragma unroll
                for (int ni = 0; ni < 2; ++ni) {
                    mma_bf16(acc[mi][ni], ah[mi], bh[ni], bh[ni + 2]);
                    mma_bf16(acc[mi][ni], ah[mi], bl[ni], bl[ni + 2]);
                    mma_bf16(acc[mi][ni], al[mi], bh[ni], bh[ni + 2]);
                }
        }
    }

    // epilogue: D[j][c] -> g_FTp
    float* outp = g_FTp + ((size_t)(b * NCH + ch)) * NJ * NC;
#pragma unroll
    for (int mi = 0; mi < 4; ++mi)
#pragma unroll
        for (int ni = 0; ni < 2; ++ni) {
            int jrow = j0 + 16 * mi + (lane >> 2);
            int ccol = c0 + 8 * ni + 2 * (lane & 3);
            float2 v0 = make_float2(acc[mi][ni][0], acc[mi][ni][1]);
            float2 v1 = make_float2(acc[mi][ni][2], acc[mi][ni][3]);
            *reinterpret_cast<float2*>(&outp[jrow * NC + ccol])       = v0;
            *reinterpret_cast<float2*>(&outp[(jrow + 8) * NC + ccol]) = v1;
        }
}

// ---------------------------------------------------------------------------
// Mix: reduce chunk partials, apply complex weights, fold signs, scale 64.
// ---------------------------------------------------------------------------
__global__ __launch_bounds__(64) void mix_kernel(const float* __restrict__ w1,
                                                 const float* __restrict__ w2) {
    const int k  = blockIdx.x;
    const int br = blockIdx.y;
    const int b  = blockIdx.z;
    const int o  = threadIdx.x;

    __shared__ float Ac[NC], As[NC];

    for (int v = threadIdx.x; v < 2 * NC; v += 64) {
        int cs = v >> 6;
        int i  = v & 63;
        int j  = br * 64 + cs * 32 + k;
        float s = 0.f;
        const float* basep = g_FTp + (size_t)b * NCH * NJ * NC + (size_t)j * NC + i;
        for (int c2 = 0; c2 < NCH; ++c2) s += basep[(size_t)c2 * NJ * NC];
        if (cs == 0) Ac[i] = s; else As[i] = s;
    }
    __syncthreads();

    const float* W = (br == 0) ? w1 : w2;
    float mr = 0.f, mi = 0.f;
    for (int i = 0; i < NC; ++i) {
        float2 w = *reinterpret_cast<const float2*>(W + (((size_t)i * 64 + o) * 32 + k) * 2);
        float ac = Ac[i], as = As[i];
        mr = fmaf(ac, w.x, mr);
        mr = fmaf(as, w.y, mr);
        mi = fmaf(ac, w.y, mi);
        mi = fmaf(-as, w.x, mi);
    }
    g_MY[((size_t)b * NJ + br * 64 + k) * NC + o]      = 64.f * mr;
    g_MY[((size_t)b * NJ + br * 64 + 32 + k) * NC + o] = -64.f * mi;
}

// ---------------------------------------------------------------------------
// Inverse: out[b][o][n] = sum_j MY[j][o] * Bas_out[j][n]
// HMMA with M = o (A = MY [64 o][128 j]), N = n (B = basis [128 n][128 j]).
// D frag cols = n -> direct coalesced float2 STG.
// ---------------------------------------------------------------------------
__global__ __launch_bounds__(256) void inv_kernel(const float* __restrict__ x_out,
                                                  float* __restrict__ out) {
    const int b = blockIdx.y, ch = blockIdx.x;
    const int tid = threadIdx.x, wid = tid >> 5, lane = tid & 31;

    __nv_bfloat16* AH = (__nv_bfloat16*)(dsm + I_AHI);
    __nv_bfloat16* AL = (__nv_bfloat16*)(dsm + I_ALO);

    // stage MY once: [o rows][j cols], hi/lo
    for (int v = tid; v < NJ * NC; v += 256) {
        int o = v & 63;
        int j = v >> 6;
        float val = g_MY[((size_t)b * NJ + j) * NC + o];
        __nv_bfloat16 h, l;
        split_bf16(val, h, l);
        AH[o * INV_S + j] = h;
        AL[o * INV_S + j] = l;
    }

    const int o0 = (wid & 3) * 16;
    const int nh = (wid >> 2) * 64;

    const uint32_t base = smem_u32(dsm);
    const uint32_t a_row = (uint32_t)(o0 + (lane & 7) + ((lane >> 3) & 1) * 8);
    const uint32_t kcol = (uint32_t)((lane >> 4) * 8);
    const uint32_t AHIa = base + I_AHI + (a_row * INV_S + kcol) * 2;
    const uint32_t ALOa = base + I_ALO + (a_row * INV_S + kcol) * 2;
    const uint32_t b_row = (uint32_t)(nh + (lane & 7) + ((lane >> 3) & 1) * 8);
    const uint32_t BHIa = base + I_BHI + (b_row * INV_S + kcol) * 2;
    const uint32_t BLOa = base + I_BLO + (b_row * INV_S + kcol) * 2;

    for (int t = 0; t < INV_TILES; ++t) {
        const int n0 = ch * INV_CHUNK + t * INV_TN;
        __syncthreads();
        // --- stage basis [128 n][128 j] via chains, 2 chains/thread, vector STS ---
#pragma unroll
        for (int r = 0; r < 2; ++r) {
            int id  = tid + r * 256;
            int n   = id & 127;
            int cbr = (id >> 7) & 1;
            int ckh = id >> 8;
            float p = x_out[((size_t)b * NPTS + n0 + n) * 2 + cbr];
            float c1r, c1i;
            {
                float f = p - rintf(p);
                __sincosf(TWO_PI_F * f, &c1i, &c1r);
            }
            float cr, ci;
            if (ckh == 0) { cr = 1.f; ci = 0.f; }
            else {
                float f = 16.f * p;
                f -= rintf(f);
                __sincosf(TWO_PI_F * f, &ci, &cr);
            }
            uint32_t chb[8], clb[8], shb[8], slb[8];
#pragma unroll
            for (int kp = 0; kp < 8; ++kp) {
                __nv_bfloat16 hc0, lc0, hs0, ls0, hc1, lc1, hs1, ls1;
                split_bf16(cr, hc0, lc0);
                split_bf16(ci, hs0, ls0);
                {
                    float nr = fmaf(cr, c1r, -ci * c1i);
                    float ni_ = fmaf(cr, c1i, ci * c1r);
                    cr = nr; ci = ni_;
                }
                split_bf16(cr, hc1, lc1);
                split_bf16(ci, hs1, ls1);
                {
                    float nr = fmaf(cr, c1r, -ci * c1i);
                    float ni_ = fmaf(cr, c1i, ci * c1r);
                    cr = nr; ci = ni_;
                }
                chb[kp] = pk2(hc0, hc1);
                clb[kp] = pk2(lc0, lc1);
                shb[kp] = pk2(hs0, hs1);
                slb[kp] = pk2(ls0, ls1);
            }
            // row n, cos cols (cbr*64 + ckh*16 + k), sin +32  -> byte offsets
            uint32_t rowb = (uint32_t)(n * (INV_S * 2) + cbr * 128 + ckh * 32);
            char* BHp = dsm + I_BHI + rowb;
            char* BLp = dsm + I_BLO + rowb;
            *reinterpret_cast<uint4*>(BHp)          = *reinterpret_cast<uint4*>(&chb[0]);
            *reinterpret_cast<uint4*>(BHp + 16)     = *reinterpret_cast<uint4*>(&chb[4]);
            *reinterpret_cast<uint4*>(BLp)          = *reinterpret_cast<uint4*>(&clb[0]);
            *reinterpret_cast<uint4*>(BLp + 16)     = *reinterpret_cast<uint4*>(&clb[4]);
            *reinterpret_cast<uint4*>(BHp + 64)     = *reinterpret_cast<uint4*>(&shb[0]);
            *reinterpret_cast<uint4*>(BHp + 64 + 16)= *reinterpret_cast<uint4*>(&shb[4]);
            *reinterpret_cast<uint4*>(BLp + 64)     = *reinterpret_cast<uint4*>(&slb[0]);
            *reinterpret_cast<uint4*>(BLp + 64 + 16)= *reinterpret_cast<uint4*>(&slb[4]);
        }
        __syncthreads();

        // --- MMA: K = j = 128, 8 k-steps ---
        float acc[8][4];
#pragma unroll
        for (int ni = 0; ni < 8; ++ni)
#pragma unroll
            for (int q = 0; q < 4; ++q) acc[ni][q] = 0.f;

#pragma unroll
        for (int ks = 0; ks < 8; ++ks) {
            const uint32_t co = (uint32_t)(ks * 16 * 2);
            uint32_t ah[4], al[4], bh[4][4], bl[4][4];
            ldsm4(ah, AHIa + co);
            ldsm4(al, ALOa + co);
#pragma unroll
            for (int g = 0; g < 4; ++g) {
                ldsm4(bh[g], BHIa + g * (16 * INV_S * 2) + co);
                ldsm4(bl[g], BLOa + g * (16 * INV_S * 2) + co);
            }
#pragma unroll
            for (int ni = 0; ni < 8; ++ni) {
                int g = ni >> 1, h = ni & 1;
                mma_bf16(acc[ni], ah, bh[g][h], bh[g][h + 2]);
                mma_bf16(acc[ni], ah, bl[g][h], bl[g][h + 2]);
                mma_bf16(acc[ni], al, bh[g][h], bh[g][h + 2]);
            }
        }

        // --- epilogue: direct coalesced STG ---
        const int orow = o0 + (lane >> 2);
#pragma unroll
        for (int ni = 0; ni < 8; ++ni) {
            int n = n0 + nh + 8 * ni + 2 * (lane & 3);
            float2 v0 = make_float2(acc[ni][0], acc[ni][1]);
            float2 v1 = make_float2(acc[ni][2], acc[ni][3]);
            *reinterpret_cast<float2*>(&out[((size_t)(b * NC + orow)) * NPTS + n])     = v0;
            *reinterpret_cast<float2*>(&out[((size_t)(b * NC + orow + 8)) * NPTS + n]) = v1;
        }
    }
}

// ---------------------------------------------------------------------------
extern "C" void kernel_launch(void* const* d_in, const int* in_sizes, int n_in,
                              void* d_out, int out_size) {
    const float* x     = (const float*)d_in[0];
    const float* x_in  = (const float*)d_in[1];
    const float* x_out = (const float*)d_in[2];
    const float* w1    = (const float*)d_in[3];
    const float* w2    = (const float*)d_in[4];
    float* out = (float*)d_out;

    cudaFuncSetAttribute(fwd_kernel, cudaFuncAttributeMaxDynamicSharedMemorySize, F_TOT);
    cudaFuncSetAttribute(inv_kernel, cudaFuncAttributeMaxDynamicSharedMemorySize, I_TOT);

    fwd_kernel<<<dim3(NCH, NB), 256, F_TOT>>>(x, x_in);
    mix_kernel<<<dim3(32, 2, NB), 64>>>(w1, w2);
    inv_kernel<<<dim3(NCHI, NB), 256, I_TOT>>>(x_out, out);
}